// round 15
// baseline (speedup 1.0000x reference)
#include <cuda_runtime.h>
#include <cuda_fp16.h>
#include <math.h>
#include <stdint.h>

#define BB 2
#define LQn 2048
#define LKn 2048
#define EE 1024
#define HH 16
#define DD 64

// ---------------- scratch (f16) ----------------
__device__ __half g_Q[(size_t)BB * LQn * EE];
__device__ __half g_K[(size_t)BB * LKn * EE];
__device__ __half g_V[(size_t)BB * LKn * EE];
__device__ __half g_ctx[(size_t)BB * LQn * EE];
__device__ __half g_P[(size_t)BB * HH * LQn * LKn];
__device__ __half g_Wh[(size_t)4 * EE * EE];
__device__ __half g_X[(size_t)3 * BB * LQn * EE];
__device__ uint32_t g_M[(size_t)BB * LQn * (LKn / 32)];
__device__ float g_stats[(size_t)BB * HH * LQn];
__device__ float g_Sraw[(size_t)BB * HH * LQn * LKn];

// ---------------- helpers ----------------
__device__ __forceinline__ uint32_t h2(float x, float y) {
    __half2 h = __floats2half2_rn(x, y);
    return *(uint32_t*)&h;
}
__device__ __forceinline__ void mma16(float* d, uint32_t a0, uint32_t a1,
                                      uint32_t a2, uint32_t a3,
                                      uint32_t b0, uint32_t b1) {
    asm volatile(
        "mma.sync.aligned.m16n8k16.row.col.f32.f16.f16.f32 "
        "{%0,%1,%2,%3},{%4,%5,%6,%7},{%8,%9},{%0,%1,%2,%3};"
        : "+f"(d[0]), "+f"(d[1]), "+f"(d[2]), "+f"(d[3])
        : "r"(a0), "r"(a1), "r"(a2), "r"(a3), "r"(b0), "r"(b1));
}
__device__ __forceinline__ uint32_t smem_u32p(const void* p) {
    uint32_t a;
    asm("{ .reg .u64 t; cvta.to.shared.u64 t, %1; cvt.u32.u64 %0, t; }"
        : "=r"(a) : "l"(p));
    return a;
}
#define LDM4(d0, d1, d2, d3, a)                                            \
    asm volatile("ldmatrix.sync.aligned.m8n8.x4.shared.b16 {%0,%1,%2,%3}, [%4];" \
                 : "=r"(d0), "=r"(d1), "=r"(d2), "=r"(d3) : "r"(a))
#define LDM4T(d0, d1, d2, d3, a)                                           \
    asm volatile("ldmatrix.sync.aligned.m8n8.x4.trans.shared.b16 {%0,%1,%2,%3}, [%4];" \
                 : "=r"(d0), "=r"(d1), "=r"(d2), "=r"(d3) : "r"(a))
#define CP16(dst, src)                                                     \
    asm volatile("cp.async.cg.shared.global [%0], [%1], 16;"               \
                 :: "r"(dst), "l"(src))
#define CP_COMMIT() asm volatile("cp.async.commit_group;" ::: "memory")
#define CP_WAIT0()  asm volatile("cp.async.wait_group 0;" ::: "memory")

// ---------------- converters ----------------
__global__ __launch_bounds__(256) void conv_w(
    const float* __restrict__ w0, const float* __restrict__ w1,
    const float* __restrict__ w2, const float* __restrict__ w3)
{
    const float* src = (blockIdx.y == 0) ? w0 : (blockIdx.y == 1) ? w1
                     : (blockIdx.y == 2) ? w2 : w3;
    __half* dst = g_Wh + (size_t)blockIdx.y * EE * EE;
    size_t i = ((size_t)blockIdx.x * 256 + threadIdx.x) * 4;
    float4 v = *(const float4*)(src + i);
    *(uint2*)(dst + i) = make_uint2(h2(v.x, v.y), h2(v.z, v.w));
}
__global__ __launch_bounds__(256) void conv_x(
    const float* __restrict__ x0, const float* __restrict__ x1,
    const float* __restrict__ x2)
{
    const float* src = (blockIdx.y == 0) ? x0 : (blockIdx.y == 1) ? x1 : x2;
    __half* dst = g_X + (size_t)blockIdx.y * BB * LQn * EE;
    size_t i = ((size_t)blockIdx.x * 256 + threadIdx.x) * 4;
    float4 v = *(const float4*)(src + i);
    *(uint2*)(dst + i) = make_uint2(h2(v.x, v.y), h2(v.z, v.w));
}
__global__ __launch_bounds__(256) void conv_mask(const int* __restrict__ mask)
{
    size_t i = (size_t)blockIdx.x * 256 + threadIdx.x;
    int v = mask[i] != 0;
    uint32_t bits = __ballot_sync(0xFFFFFFFF, v);
    if ((threadIdx.x & 31) == 0) g_M[i >> 5] = bits;
}

// ============ f16 GEMM core: K-chunk 64, dynamic smem double-buffer ============
#define GST 72
#define GTILE (128 * GST * 2)          // bytes per tile buffer
#define GEMM_DYN (4 * GTILE)           // A/W x 2 buffers

template <bool OUT_F32>
__device__ __forceinline__ void gemm_body(
    const __half* __restrict__ A, const __half* __restrict__ W,
    const float* __restrict__ bias, void* __restrict__ Cv,
    int m0, int n0)
{
    extern __shared__ __align__(16) char gsm[];
    const uint32_t sb = smem_u32p(gsm);
    const uint32_t as_b[2] = {sb, sb + GTILE};
    const uint32_t ws_b[2] = {sb + 2 * GTILE, sb + 3 * GTILE};

    const int tid = threadIdx.x;
    const int lane = tid & 31;
    const int w = tid >> 5;
    const int wm = w >> 1, wn = w & 1;
    const int qr = lane >> 2;
    const int qc = 2 * (lane & 3);
    const int l7 = lane & 7;
    const int bit3 = ((lane >> 3) & 1) * 8;
    const int bit4 = ((lane >> 4) & 1) * 8;

    const __half* Ap = A + (size_t)(m0 + tid) * EE;
    const __half* Wp = W + (size_t)(n0 + tid) * EE;
    const uint32_t cpoff = (uint32_t)(tid * GST * 2);

    // prefetch chunk 0 (64 halves = 128 B per row)
#pragma unroll
    for (int i = 0; i < 8; i++) {
        CP16(as_b[0] + cpoff + i * 16, (const char*)Ap + i * 16);
        CP16(ws_b[0] + cpoff + i * 16, (const char*)Wp + i * 16);
    }
    CP_COMMIT();

    float acc[4][8][4];
#pragma unroll
    for (int mi = 0; mi < 4; mi++)
#pragma unroll
        for (int ni = 0; ni < 8; ni++)
#pragma unroll
            for (int e = 0; e < 4; e++) acc[mi][ni][e] = 0.0f;

    for (int kc = 0; kc < 16; kc++) {
        const int buf = kc & 1;
        CP_WAIT0();
        __syncthreads();
        if (kc < 15) {
            const char* an = (const char*)(Ap + (kc + 1) * 64);
            const char* wn2 = (const char*)(Wp + (kc + 1) * 64);
#pragma unroll
            for (int i = 0; i < 8; i++) {
                CP16(as_b[buf ^ 1] + cpoff + i * 16, an + i * 16);
                CP16(ws_b[buf ^ 1] + cpoff + i * 16, wn2 + i * 16);
            }
            CP_COMMIT();
        }
#pragma unroll
        for (int ks = 0; ks < 4; ks++) {
            uint32_t af[4][4];
#pragma unroll
            for (int mi = 0; mi < 4; mi++) {
                uint32_t a = as_b[buf] +
                    ((wm * 64 + mi * 16 + bit3 + l7) * GST + ks * 16 + bit4) * 2;
                LDM4(af[mi][0], af[mi][1], af[mi][2], af[mi][3], a);
            }
#pragma unroll
            for (int nii = 0; nii < 4; nii++) {
                uint32_t b0, b1, b2, b3;
                uint32_t a = ws_b[buf] +
                    ((wn * 64 + nii * 16 + bit4 + l7) * GST + ks * 16 + bit3) * 2;
                LDM4(b0, b1, b2, b3, a);
#pragma unroll
                for (int mi = 0; mi < 4; mi++) {
                    mma16(acc[mi][2 * nii],     af[mi][0], af[mi][1], af[mi][2], af[mi][3], b0, b1);
                    mma16(acc[mi][2 * nii + 1], af[mi][0], af[mi][1], af[mi][2], af[mi][3], b2, b3);
                }
            }
        }
        __syncthreads();
    }

#pragma unroll
    for (int mi = 0; mi < 4; mi++) {
        int rl = m0 + wm * 64 + mi * 16 + qr;
#pragma unroll
        for (int ni = 0; ni < 8; ni++) {
            int cc = n0 + wn * 64 + ni * 8 + qc;
            float2 bv = *(const float2*)&bias[cc];
            if (OUT_F32) {
                float* C = (float*)Cv;
                *(float2*)&C[(size_t)rl * EE + cc] =
                    make_float2(acc[mi][ni][0] + bv.x, acc[mi][ni][1] + bv.y);
                *(float2*)&C[(size_t)(rl + 8) * EE + cc] =
                    make_float2(acc[mi][ni][2] + bv.x, acc[mi][ni][3] + bv.y);
            } else {
                __half* C = (__half*)Cv;
                *(uint32_t*)&C[(size_t)rl * EE + cc] =
                    h2(acc[mi][ni][0] + bv.x, acc[mi][ni][1] + bv.y);
                *(uint32_t*)&C[(size_t)(rl + 8) * EE + cc] =
                    h2(acc[mi][ni][2] + bv.x, acc[mi][ni][3] + bv.y);
            }
        }
    }
}

__global__ __launch_bounds__(128, 2) void gemm_qkv(
    const float* __restrict__ b0p, const float* __restrict__ b1p,
    const float* __restrict__ b2p)
{
    const int z = blockIdx.z;
    const __half* A = g_X + (size_t)z * BB * LQn * EE;
    const __half* W = g_Wh + (size_t)z * EE * EE;
    const float* bias = (z == 0) ? b0p : (z == 1) ? b1p : b2p;
    __half* C = (z == 0) ? g_Q : (z == 1) ? g_K : g_V;
    gemm_body<false>(A, W, bias, C, blockIdx.y * 128, blockIdx.x * 128);
}

__global__ __launch_bounds__(128, 2) void gemm_out(
    const float* __restrict__ bias, float* __restrict__ C)
{
    gemm_body<true>(g_ctx, g_Wh + (size_t)3 * EE * EE, bias, C,
                    blockIdx.y * 128, blockIdx.x * 128);
}

// ============ Attention (f16 mma + ldmatrix + cp.async + bitmask) ============
#define QP 72
#define TILE_B (128 * QP * 2)
#define ATT_DYN (5 * TILE_B + 1024)

__global__ __launch_bounds__(256, 1) void attn_tc()
{
    extern __shared__ char smc[];
    float* lred = (float*)(smc + 5 * TILE_B);
    float* Osm = (float*)smc;

    const uint32_t sb = smem_u32p(smc);
    const uint32_t qs_b = sb;
    const uint32_t ks_b[2] = {sb + TILE_B, sb + 2 * TILE_B};
    const uint32_t vs_b[2] = {sb + 3 * TILE_B, sb + 4 * TILE_B};

    const int tid = threadIdx.x;
    const int lane = tid & 31;
    const int w = tid >> 5;
    const int qr = lane >> 2;
    const int qc = 2 * (lane & 3);
    const int wq = w >> 1;
    const int wk = w & 1;
    const int qb = wq * 32;
    const int l7 = lane & 7;
    const int bit3 = ((lane >> 3) & 1) * 8;
    const int bit4 = ((lane >> 4) & 1) * 8;

    const int q0 = blockIdx.x * 128;
    const int h = blockIdx.y;
    const int b = blockIdx.z;

    const int cr = tid >> 1;
    const int cc32 = (tid & 1) * 32;
    const uint32_t cpdst = (uint32_t)((cr * QP + cc32) * 2);

    const __half* Kg0 = g_K + (size_t)(b * LKn + cr) * EE + h * DD + cc32;
    const __half* Vg0 = g_V + (size_t)(b * LKn + cr) * EE + h * DD + cc32;

    {
#pragma unroll
        for (int i = 0; i < 4; i++) {
            CP16(ks_b[0] + cpdst + i * 16, (const char*)Kg0 + i * 16);
            CP16(vs_b[0] + cpdst + i * 16, (const char*)Vg0 + i * 16);
        }
        CP_COMMIT();
    }
    {
        __half* Qs = (__half*)smc;
        const __half* Qg = g_Q + (size_t)(b * LQn + q0 + cr) * EE + h * DD + cc32;
        uint4* dst = (uint4*)&Qs[cr * QP + cc32];
        const uint4* src = (const uint4*)Qg;
#pragma unroll
        for (int i = 0; i < 4; i++) dst[i] = src[i];
    }

    float oacc[2][8][4];
#pragma unroll
    for (int mi = 0; mi < 2; mi++)
#pragma unroll
        for (int ni = 0; ni < 8; ni++)
#pragma unroll
            for (int e = 0; e < 4; e++) oacc[mi][ni][e] = 0.0f;

    float lacc[2][2] = {{0.0f, 0.0f}, {0.0f, 0.0f}};

    const uint32_t* bmp[2][2];
    __half* pptr[2][2];
#pragma unroll
    for (int mi = 0; mi < 2; mi++)
#pragma unroll
        for (int hi = 0; hi < 2; hi++) {
            int q = q0 + qb + mi * 16 + hi * 8 + qr;
            bmp[mi][hi] = g_M + (size_t)(b * LQn + q) * (LKn / 32) + wk * 2;
            pptr[mi][hi] = g_P + ((size_t)(b * HH + h) * LQn + q) * LKn + wk * 64;
        }

    for (int c = 0; c < 16; c++) {
        const int buf = c & 1;
        CP_WAIT0();
        __syncthreads();
        if (c < 15) {
            const char* ks = (const char*)(Kg0 + (size_t)(c + 1) * 128 * EE);
            const char* vs = (const char*)(Vg0 + (size_t)(c + 1) * 128 * EE);
#pragma unroll
            for (int i = 0; i < 4; i++) {
                CP16(ks_b[buf ^ 1] + cpdst + i * 16, ks + i * 16);
                CP16(vs_b[buf ^ 1] + cpdst + i * 16, vs + i * 16);
            }
            CP_COMMIT();
        }

        uint2 bmv[2][2];
#pragma unroll
        for (int mi = 0; mi < 2; mi++)
#pragma unroll
            for (int hi = 0; hi < 2; hi++)
                bmv[mi][hi] = *(const uint2*)(bmp[mi][hi] + c * 4);

        float sacc[2][8][4];
#pragma unroll
        for (int mi = 0; mi < 2; mi++)
#pragma unroll
            for (int ni = 0; ni < 8; ni++)
#pragma unroll
                for (int e = 0; e < 4; e++) sacc[mi][ni][e] = 0.0f;

#pragma unroll
        for (int ks = 0; ks < 4; ks++) {
            uint32_t af[2][4];
#pragma unroll
            for (int mi = 0; mi < 2; mi++) {
                uint32_t a = qs_b + ((qb + mi * 16 + bit3 + l7) * QP + ks * 16 + bit4) * 2;
                LDM4(af[mi][0], af[mi][1], af[mi][2], af[mi][3], a);
            }
#pragma unroll
            for (int nii = 0; nii < 4; nii++) {
                uint32_t b0, b1, b2, b3;
                uint32_t a = ks_b[buf] + ((wk * 64 + nii * 16 + bit4 + l7) * QP + ks * 16 + bit3) * 2;
                LDM4(b0, b1, b2, b3, a);
                mma16(sacc[0][2 * nii],     af[0][0], af[0][1], af[0][2], af[0][3], b0, b1);
                mma16(sacc[1][2 * nii],     af[1][0], af[1][1], af[1][2], af[1][3], b0, b1);
                mma16(sacc[0][2 * nii + 1], af[0][0], af[0][1], af[0][2], af[0][3], b2, b3);
                mma16(sacc[1][2 * nii + 1], af[1][0], af[1][1], af[1][2], af[1][3], b2, b3);
            }
        }

#pragma unroll
        for (int mi = 0; mi < 2; mi++) {
#pragma unroll
            for (int ni = 0; ni < 8; ni++) {
                int cb = ni * 8 + qc;
                int sh = (ni & 3) * 8 + qc;
                uint32_t w0 = (ni < 4) ? bmv[mi][0].x : bmv[mi][0].y;
                uint32_t w1 = (ni < 4) ? bmv[mi][1].x : bmv[mi][1].y;
                float s0 = sacc[mi][ni][0] * 0.125f; if (!((w0 >> sh) & 1)) s0 = -1.0e30f;
                float s1 = sacc[mi][ni][1] * 0.125f; if (!((w0 >> (sh + 1)) & 1)) s1 = -1.0e30f;
                float s2 = sacc[mi][ni][2] * 0.125f; if (!((w1 >> sh) & 1)) s2 = -1.0e30f;
                float s3 = sacc[mi][ni][3] * 0.125f; if (!((w1 >> (sh + 1)) & 1)) s3 = -1.0e30f;
                float p0 = __expf(s0), p1 = __expf(s1);
                float p2 = __expf(s2), p3 = __expf(s3);
                *(uint32_t*)(pptr[mi][0] + c * 128 + cb) = h2(p0, p1);
                *(uint32_t*)(pptr[mi][1] + c * 128 + cb) = h2(p2, p3);
                lacc[mi][0] += p0 + p1;
                lacc[mi][1] += p2 + p3;
                sacc[mi][ni][0] = p0; sacc[mi][ni][1] = p1;
                sacc[mi][ni][2] = p2; sacc[mi][ni][3] = p3;
            }
        }

#pragma unroll
        for (int j = 0; j < 4; j++) {
            uint32_t a0[2], a1[2], a2[2], a3[2];
#pragma unroll
            for (int mi = 0; mi < 2; mi++) {
                a0[mi] = h2(sacc[mi][2 * j][0], sacc[mi][2 * j][1]);
                a1[mi] = h2(sacc[mi][2 * j][2], sacc[mi][2 * j][3]);
                a2[mi] = h2(sacc[mi][2 * j + 1][0], sacc[mi][2 * j + 1][1]);
                a3[mi] = h2(sacc[mi][2 * j + 1][2], sacc[mi][2 * j + 1][3]);
            }
#pragma unroll
            for (int nii = 0; nii < 4; nii++) {
                uint32_t b0, b1, b2, b3;
                uint32_t a = vs_b[buf] + ((wk * 64 + j * 16 + bit3 + l7) * QP + nii * 16 + bit4) * 2;
                LDM4T(b0, b1, b2, b3, a);
                mma16(oacc[0][2 * nii],     a0[0], a1[0], a2[0], a3[0], b0, b1);
                mma16(oacc[1][2 * nii],     a0[1], a1[1], a2[1], a3[1], b0, b1);
                mma16(oacc[0][2 * nii + 1], a0[0], a1[0], a2[0], a3[0], b2, b3);
                mma16(oacc[1][2 * nii + 1], a0[1], a1[1], a2[1], a3[1], b2, b3);
            }
        }
    }

#pragma unroll
    for (int mi = 0; mi < 2; mi++)
#pragma unroll
        for (int hi = 0; hi < 2; hi++) {
            float v = lacc[mi][hi];
            v += __shfl_xor_sync(0xFFFFFFFF, v, 1);
            v += __shfl_xor_sync(0xFFFFFFFF, v, 2);
            if ((lane & 3) == 0)
                lred[wk * 128 + qb + mi * 16 + hi * 8 + qr] = v;
        }
    __syncthreads();

    if (wk == 1) {
#pragma unroll
        for (int mi = 0; mi < 2; mi++) {
            int row = qb + mi * 16 + qr;
#pragma unroll
            for (int ni = 0; ni < 8; ni++) {
                *(float2*)&Osm[row * 68 + ni * 8 + qc] =
                    make_float2(oacc[mi][ni][0], oacc[mi][ni][1]);
                *(float2*)&Osm[(row + 8) * 68 + ni * 8 + qc] =
                    make_float2(oacc[mi][ni][2], oacc[mi][ni][3]);
            }
        }
    }
    __syncthreads();

    if (wk == 0) {
#pragma unroll
        for (int mi = 0; mi < 2; mi++) {
#pragma unroll
            for (int hi = 0; hi < 2; hi++) {
                int rrow = qb + mi * 16 + hi * 8 + qr;
                float l = lred[rrow] + lred[128 + rrow];
                float inv = 1.0f / l;
                __half* og = g_ctx + (size_t)(b * LQn + q0 + rrow) * EE + h * DD;
#pragma unroll
                for (int ni = 0; ni < 8; ni++) {
                    float2 part = *(const float2*)&Osm[rrow * 68 + ni * 8 + qc];
                    *(uint32_t*)&og[ni * 8 + qc] = h2(
                        (oacc[mi][ni][hi * 2 + 0] + part.x) * inv,
                        (oacc[mi][ni][hi * 2 + 1] + part.y) * inv);
                }
                if ((lane & 3) == 0)
                    g_stats[(size_t)(b * HH + h) * LQn + q0 + rrow] = l;
            }
        }
    }
}

// ---------------- normalize ----------------
__global__ __launch_bounds__(256) void attn_norm(float* __restrict__ attn)
{
    size_t i8 = (size_t)blockIdx.x * blockDim.x + threadIdx.x;
    size_t row = (i8 * 8) >> 11;
    float invl = 1.0f / g_stats[row];
    uint4 pv = *(const uint4*)(g_P + i8 * 8);
    float2 f0 = __half22float2(*(__half2*)&pv.x);
    float2 f1 = __half22float2(*(__half2*)&pv.y);
    float2 f2 = __half22float2(*(__half2*)&pv.z);
    float2 f3 = __half22float2(*(__half2*)&pv.w);
    float4* op = (float4*)(attn + i8 * 8);
    op[0] = make_float4(f0.x * invl, f0.y * invl, f1.x * invl, f1.y * invl);
    op[1] = make_float4(f2.x * invl, f2.y * invl, f3.x * invl, f3.y * invl);
}

// ---------------- launch ----------------
extern "C" void kernel_launch(void* const* d_in, const int* in_sizes, int n_in,
                              void* d_out, int out_size)
{
    const float* q_in = (const float*)d_in[0];
    const float* k_in = (const float*)d_in[1];
    const float* v_in = (const float*)d_in[2];
    const int*   mask = (const int*)d_in[3];
    const float* Wq = (const float*)d_in[4];
    const float* bq = (const float*)d_in[5];
    const float* Wk = (const float*)d_in[6];
    const float* bk = (const float*)d_in[7];
    const float* Wv = (const float*)d_in[8];
    const float* bv = (const float*)d_in[9];
    const float* Wo = (const float*)d_in[10];
    const float* bo = (const float*)d_in[11];

    float* out = (float*)d_out;

    float* gSraw;
    cudaGetSymbolAddress((void**)&gSraw, g_Sraw);

    const size_t OUT_ELEMS = (size_t)BB * LQn * EE;
    const size_t ATT_ELEMS = (size_t)BB * HH * LQn * LKn;
    bool attn_is_output = ((size_t)out_size >= OUT_ELEMS + ATT_ELEMS);
    float* attnp = attn_is_output ? (out + OUT_ELEMS) : gSraw;

    cudaFuncSetAttribute(attn_tc, cudaFuncAttributeMaxDynamicSharedMemorySize, ATT_DYN);
    cudaFuncSetAttribute(gemm_qkv, cudaFuncAttributeMaxDynamicSharedMemorySize, GEMM_DYN);
    cudaFuncSetAttribute(gemm_out, cudaFuncAttributeMaxDynamicSharedMemorySize, GEMM_DYN);

    static cudaStream_t s2 = nullptr;
    static cudaEvent_t evFork = nullptr, evJoin = nullptr;
    if (!s2) {
        cudaStreamCreateWithFlags(&s2, cudaStreamNonBlocking);
        cudaEventCreateWithFlags(&evFork, cudaEventDisableTiming);
        cudaEventCreateWithFlags(&evJoin, cudaEventDisableTiming);
    }

    conv_w<<<dim3(EE * EE / 1024, 4), 256>>>(Wq, Wk, Wv, Wo);
    conv_x<<<dim3(BB * LQn * EE / 1024, 3), 256>>>(q_in, k_in, v_in);
    conv_mask<<<(int)((size_t)BB * LQn * LKn / 256), 256>>>(mask);

    dim3 qkvGrid(8, 32, 3);
    gemm_qkv<<<qkvGrid, 128, GEMM_DYN>>>(bq, bk, bv);

    dim3 attnGrid(LQn / 128, HH, BB);
    attn_tc<<<attnGrid, 256, ATT_DYN>>>();

    cudaEventRecord(evFork, 0);
    cudaStreamWaitEvent(s2, evFork, 0);

    size_t total8 = ATT_ELEMS / 8;
    attn_norm<<<(int)((total8 + 255) / 256), 256, 0, s2>>>(attnp);

    gemm_out<<<dim3(8, 32), 128, GEMM_DYN>>>(bo, out);

    cudaEventRecord(evJoin, s2);
    cudaStreamWaitEvent(0, evJoin, 0);
}

// round 16
// speedup vs baseline: 1.0542x; 1.0542x over previous
#include <cuda_runtime.h>
#include <cuda_fp16.h>
#include <math.h>
#include <stdint.h>

#define BB 2
#define LQn 2048
#define LKn 2048
#define EE 1024
#define HH 16
#define DD 64

// ---------------- scratch (f16) ----------------
__device__ __half g_Q[(size_t)BB * LQn * EE];
__device__ __half g_K[(size_t)BB * LKn * EE];
__device__ __half g_V[(size_t)BB * LKn * EE];
__device__ __half g_ctx[(size_t)BB * LQn * EE];
__device__ __half g_P[(size_t)BB * HH * LQn * LKn];
__device__ __half g_Wh[(size_t)4 * EE * EE];
__device__ __half g_X[(size_t)3 * BB * LQn * EE];
__device__ uint32_t g_M[(size_t)BB * LQn * (LKn / 32)];
__device__ float g_stats[(size_t)BB * HH * LQn];
__device__ float g_Sraw[(size_t)BB * HH * LQn * LKn];

// ---------------- helpers ----------------
__device__ __forceinline__ uint32_t h2(float x, float y) {
    __half2 h = __floats2half2_rn(x, y);
    return *(uint32_t*)&h;
}
__device__ __forceinline__ void mma16(float* d, uint32_t a0, uint32_t a1,
                                      uint32_t a2, uint32_t a3,
                                      uint32_t b0, uint32_t b1) {
    asm volatile(
        "mma.sync.aligned.m16n8k16.row.col.f32.f16.f16.f32 "
        "{%0,%1,%2,%3},{%4,%5,%6,%7},{%8,%9},{%0,%1,%2,%3};"
        : "+f"(d[0]), "+f"(d[1]), "+f"(d[2]), "+f"(d[3])
        : "r"(a0), "r"(a1), "r"(a2), "r"(a3), "r"(b0), "r"(b1));
}
__device__ __forceinline__ uint32_t smem_u32p(const void* p) {
    uint32_t a;
    asm("{ .reg .u64 t; cvta.to.shared.u64 t, %1; cvt.u32.u64 %0, t; }"
        : "=r"(a) : "l"(p));
    return a;
}
#define LDM4(d0, d1, d2, d3, a)                                            \
    asm volatile("ldmatrix.sync.aligned.m8n8.x4.shared.b16 {%0,%1,%2,%3}, [%4];" \
                 : "=r"(d0), "=r"(d1), "=r"(d2), "=r"(d3) : "r"(a))
#define LDM4T(d0, d1, d2, d3, a)                                           \
    asm volatile("ldmatrix.sync.aligned.m8n8.x4.trans.shared.b16 {%0,%1,%2,%3}, [%4];" \
                 : "=r"(d0), "=r"(d1), "=r"(d2), "=r"(d3) : "r"(a))
#define CP16(dst, src)                                                     \
    asm volatile("cp.async.cg.shared.global [%0], [%1], 16;"               \
                 :: "r"(dst), "l"(src))
#define CP_COMMIT() asm volatile("cp.async.commit_group;" ::: "memory")
#define CP_WAIT0()  asm volatile("cp.async.wait_group 0;" ::: "memory")
#define CP_WAIT1()  asm volatile("cp.async.wait_group 1;" ::: "memory")

// ---------------- converters ----------------
__global__ __launch_bounds__(256) void conv_w(
    const float* __restrict__ w0, const float* __restrict__ w1,
    const float* __restrict__ w2, const float* __restrict__ w3)
{
    const float* src = (blockIdx.y == 0) ? w0 : (blockIdx.y == 1) ? w1
                     : (blockIdx.y == 2) ? w2 : w3;
    __half* dst = g_Wh + (size_t)blockIdx.y * EE * EE;
    size_t i = ((size_t)blockIdx.x * 256 + threadIdx.x) * 4;
    float4 v = *(const float4*)(src + i);
    *(uint2*)(dst + i) = make_uint2(h2(v.x, v.y), h2(v.z, v.w));
}
__global__ __launch_bounds__(256) void conv_x(
    const float* __restrict__ x0, const float* __restrict__ x1,
    const float* __restrict__ x2)
{
    const float* src = (blockIdx.y == 0) ? x0 : (blockIdx.y == 1) ? x1 : x2;
    __half* dst = g_X + (size_t)blockIdx.y * BB * LQn * EE;
    size_t i = ((size_t)blockIdx.x * 256 + threadIdx.x) * 4;
    float4 v = *(const float4*)(src + i);
    *(uint2*)(dst + i) = make_uint2(h2(v.x, v.y), h2(v.z, v.w));
}
__global__ __launch_bounds__(256) void conv_mask(const int* __restrict__ mask)
{
    size_t i = (size_t)blockIdx.x * 256 + threadIdx.x;
    int v = mask[i] != 0;
    uint32_t bits = __ballot_sync(0xFFFFFFFF, v);
    if ((threadIdx.x & 31) == 0) g_M[i >> 5] = bits;
}

// ============ f16 GEMM core: K-chunk 32, 3-stage cp.async pipeline ============
#define GST 40
#define GTILE (128 * GST * 2)          // 10240 B per tile buffer
#define GEMM_DYN (6 * GTILE)           // A x3 + W x3

template <bool OUT_F32>
__device__ __forceinline__ void gemm_body(
    const __half* __restrict__ A, const __half* __restrict__ W,
    const float* __restrict__ bias, void* __restrict__ Cv,
    int m0, int n0)
{
    extern __shared__ __align__(16) char gsm[];
    const uint32_t sb = smem_u32p(gsm);
    const uint32_t as_b[3] = {sb, sb + GTILE, sb + 2 * GTILE};
    const uint32_t ws_b[3] = {sb + 3 * GTILE, sb + 4 * GTILE, sb + 5 * GTILE};

    const int tid = threadIdx.x;
    const int lane = tid & 31;
    const int w = tid >> 5;
    const int wm = w >> 1, wn = w & 1;
    const int qr = lane >> 2;
    const int qc = 2 * (lane & 3);
    const int l7 = lane & 7;
    const int bit3 = ((lane >> 3) & 1) * 8;
    const int bit4 = ((lane >> 4) & 1) * 8;

    const __half* Ap = A + (size_t)(m0 + tid) * EE;
    const __half* Wp = W + (size_t)(n0 + tid) * EE;
    const uint32_t cpoff = (uint32_t)(tid * GST * 2);

    // prologue: prefetch chunks 0 and 1
#pragma unroll
    for (int s = 0; s < 2; s++) {
        const char* an = (const char*)(Ap + s * 32);
        const char* wn2 = (const char*)(Wp + s * 32);
#pragma unroll
        for (int i = 0; i < 4; i++) {
            CP16(as_b[s] + cpoff + i * 16, an + i * 16);
            CP16(ws_b[s] + cpoff + i * 16, wn2 + i * 16);
        }
        CP_COMMIT();
    }

    float acc[4][8][4];
#pragma unroll
    for (int mi = 0; mi < 4; mi++)
#pragma unroll
        for (int ni = 0; ni < 8; ni++)
#pragma unroll
            for (int e = 0; e < 4; e++) acc[mi][ni][e] = 0.0f;

    int buf = 0, nbuf = 2;
    for (int kc = 0; kc < 32; kc++) {
        CP_WAIT1();          // chunk kc resident (kc+1 may be in flight)
        __syncthreads();     // visibility + protects nbuf from prior readers
        if (kc < 30) {
            const char* an = (const char*)(Ap + (kc + 2) * 32);
            const char* wn2 = (const char*)(Wp + (kc + 2) * 32);
#pragma unroll
            for (int i = 0; i < 4; i++) {
                CP16(as_b[nbuf] + cpoff + i * 16, an + i * 16);
                CP16(ws_b[nbuf] + cpoff + i * 16, wn2 + i * 16);
            }
            CP_COMMIT();
        }
#pragma unroll
        for (int ks = 0; ks < 2; ks++) {
            uint32_t af[4][4];
#pragma unroll
            for (int mi = 0; mi < 4; mi++) {
                uint32_t a = as_b[buf] +
                    ((wm * 64 + mi * 16 + bit3 + l7) * GST + ks * 16 + bit4) * 2;
                LDM4(af[mi][0], af[mi][1], af[mi][2], af[mi][3], a);
            }
#pragma unroll
            for (int nii = 0; nii < 4; nii++) {
                uint32_t b0, b1, b2, b3;
                uint32_t a = ws_b[buf] +
                    ((wn * 64 + nii * 16 + bit4 + l7) * GST + ks * 16 + bit3) * 2;
                LDM4(b0, b1, b2, b3, a);
#pragma unroll
                for (int mi = 0; mi < 4; mi++) {
                    mma16(acc[mi][2 * nii],     af[mi][0], af[mi][1], af[mi][2], af[mi][3], b0, b1);
                    mma16(acc[mi][2 * nii + 1], af[mi][0], af[mi][1], af[mi][2], af[mi][3], b2, b3);
                }
            }
        }
        buf = (buf == 2) ? 0 : buf + 1;
        nbuf = (nbuf == 2) ? 0 : nbuf + 1;
    }

#pragma unroll
    for (int mi = 0; mi < 4; mi++) {
        int rl = m0 + wm * 64 + mi * 16 + qr;
#pragma unroll
        for (int ni = 0; ni < 8; ni++) {
            int cc = n0 + wn * 64 + ni * 8 + qc;
            float2 bv = *(const float2*)&bias[cc];
            if (OUT_F32) {
                float* C = (float*)Cv;
                *(float2*)&C[(size_t)rl * EE + cc] =
                    make_float2(acc[mi][ni][0] + bv.x, acc[mi][ni][1] + bv.y);
                *(float2*)&C[(size_t)(rl + 8) * EE + cc] =
                    make_float2(acc[mi][ni][2] + bv.x, acc[mi][ni][3] + bv.y);
            } else {
                __half* C = (__half*)Cv;
                *(uint32_t*)&C[(size_t)rl * EE + cc] =
                    h2(acc[mi][ni][0] + bv.x, acc[mi][ni][1] + bv.y);
                *(uint32_t*)&C[(size_t)(rl + 8) * EE + cc] =
                    h2(acc[mi][ni][2] + bv.x, acc[mi][ni][3] + bv.y);
            }
        }
    }
}

__global__ __launch_bounds__(128, 2) void gemm_qkv(
    const float* __restrict__ b0p, const float* __restrict__ b1p,
    const float* __restrict__ b2p)
{
    const int z = blockIdx.z;
    const __half* A = g_X + (size_t)z * BB * LQn * EE;
    const __half* W = g_Wh + (size_t)z * EE * EE;
    const float* bias = (z == 0) ? b0p : (z == 1) ? b1p : b2p;
    __half* C = (z == 0) ? g_Q : (z == 1) ? g_K : g_V;
    gemm_body<false>(A, W, bias, C, blockIdx.y * 128, blockIdx.x * 128);
}

__global__ __launch_bounds__(128, 2) void gemm_out(
    const float* __restrict__ bias, float* __restrict__ C)
{
    gemm_body<true>(g_ctx, g_Wh + (size_t)3 * EE * EE, bias, C,
                    blockIdx.y * 128, blockIdx.x * 128);
}

// ============ Attention (f16 mma + ldmatrix + cp.async + bitmask) ============
#define QP 72
#define TILE_B (128 * QP * 2)
#define ATT_DYN (5 * TILE_B + 1024)

__global__ __launch_bounds__(256, 1) void attn_tc()
{
    extern __shared__ char smc[];
    float* lred = (float*)(smc + 5 * TILE_B);
    float* Osm = (float*)smc;

    const uint32_t sb = smem_u32p(smc);
    const uint32_t qs_b = sb;
    const uint32_t ks_b[2] = {sb + TILE_B, sb + 2 * TILE_B};
    const uint32_t vs_b[2] = {sb + 3 * TILE_B, sb + 4 * TILE_B};

    const int tid = threadIdx.x;
    const int lane = tid & 31;
    const int w = tid >> 5;
    const int qr = lane >> 2;
    const int qc = 2 * (lane & 3);
    const int wq = w >> 1;
    const int wk = w & 1;
    const int qb = wq * 32;
    const int l7 = lane & 7;
    const int bit3 = ((lane >> 3) & 1) * 8;
    const int bit4 = ((lane >> 4) & 1) * 8;

    const int q0 = blockIdx.x * 128;
    const int h = blockIdx.y;
    const int b = blockIdx.z;

    const int cr = tid >> 1;
    const int cc32 = (tid & 1) * 32;
    const uint32_t cpdst = (uint32_t)((cr * QP + cc32) * 2);

    const __half* Kg0 = g_K + (size_t)(b * LKn + cr) * EE + h * DD + cc32;
    const __half* Vg0 = g_V + (size_t)(b * LKn + cr) * EE + h * DD + cc32;

    {
#pragma unroll
        for (int i = 0; i < 4; i++) {
            CP16(ks_b[0] + cpdst + i * 16, (const char*)Kg0 + i * 16);
            CP16(vs_b[0] + cpdst + i * 16, (const char*)Vg0 + i * 16);
        }
        CP_COMMIT();
    }
    {
        __half* Qs = (__half*)smc;
        const __half* Qg = g_Q + (size_t)(b * LQn + q0 + cr) * EE + h * DD + cc32;
        uint4* dst = (uint4*)&Qs[cr * QP + cc32];
        const uint4* src = (const uint4*)Qg;
#pragma unroll
        for (int i = 0; i < 4; i++) dst[i] = src[i];
    }

    float oacc[2][8][4];
#pragma unroll
    for (int mi = 0; mi < 2; mi++)
#pragma unroll
        for (int ni = 0; ni < 8; ni++)
#pragma unroll
            for (int e = 0; e < 4; e++) oacc[mi][ni][e] = 0.0f;

    float lacc[2][2] = {{0.0f, 0.0f}, {0.0f, 0.0f}};

    const uint32_t* bmp[2][2];
    __half* pptr[2][2];
#pragma unroll
    for (int mi = 0; mi < 2; mi++)
#pragma unroll
        for (int hi = 0; hi < 2; hi++) {
            int q = q0 + qb + mi * 16 + hi * 8 + qr;
            bmp[mi][hi] = g_M + (size_t)(b * LQn + q) * (LKn / 32) + wk * 2;
            pptr[mi][hi] = g_P + ((size_t)(b * HH + h) * LQn + q) * LKn + wk * 64;
        }

    for (int c = 0; c < 16; c++) {
        const int buf = c & 1;
        CP_WAIT0();
        __syncthreads();
        if (c < 15) {
            const char* ks = (const char*)(Kg0 + (size_t)(c + 1) * 128 * EE);
            const char* vs = (const char*)(Vg0 + (size_t)(c + 1) * 128 * EE);
#pragma unroll
            for (int i = 0; i < 4; i++) {
                CP16(ks_b[buf ^ 1] + cpdst + i * 16, ks + i * 16);
                CP16(vs_b[buf ^ 1] + cpdst + i * 16, vs + i * 16);
            }
            CP_COMMIT();
        }

        uint2 bmv[2][2];
#pragma unroll
        for (int mi = 0; mi < 2; mi++)
#pragma unroll
            for (int hi = 0; hi < 2; hi++)
                bmv[mi][hi] = *(const uint2*)(bmp[mi][hi] + c * 4);

        float sacc[2][8][4];
#pragma unroll
        for (int mi = 0; mi < 2; mi++)
#pragma unroll
            for (int ni = 0; ni < 8; ni++)
#pragma unroll
                for (int e = 0; e < 4; e++) sacc[mi][ni][e] = 0.0f;

#pragma unroll
        for (int ks = 0; ks < 4; ks++) {
            uint32_t af[2][4];
#pragma unroll
            for (int mi = 0; mi < 2; mi++) {
                uint32_t a = qs_b + ((qb + mi * 16 + bit3 + l7) * QP + ks * 16 + bit4) * 2;
                LDM4(af[mi][0], af[mi][1], af[mi][2], af[mi][3], a);
            }
#pragma unroll
            for (int nii = 0; nii < 4; nii++) {
                uint32_t b0, b1, b2, b3;
                uint32_t a = ks_b[buf] + ((wk * 64 + nii * 16 + bit4 + l7) * QP + ks * 16 + bit3) * 2;
                LDM4(b0, b1, b2, b3, a);
                mma16(sacc[0][2 * nii],     af[0][0], af[0][1], af[0][2], af[0][3], b0, b1);
                mma16(sacc[1][2 * nii],     af[1][0], af[1][1], af[1][2], af[1][3], b0, b1);
                mma16(sacc[0][2 * nii + 1], af[0][0], af[0][1], af[0][2], af[0][3], b2, b3);
                mma16(sacc[1][2 * nii + 1], af[1][0], af[1][1], af[1][2], af[1][3], b2, b3);
            }
        }

#pragma unroll
        for (int mi = 0; mi < 2; mi++) {
#pragma unroll
            for (int ni = 0; ni < 8; ni++) {
                int cb = ni * 8 + qc;
                int sh = (ni & 3) * 8 + qc;
                uint32_t w0 = (ni < 4) ? bmv[mi][0].x : bmv[mi][0].y;
                uint32_t w1 = (ni < 4) ? bmv[mi][1].x : bmv[mi][1].y;
                float s0 = sacc[mi][ni][0] * 0.125f; if (!((w0 >> sh) & 1)) s0 = -1.0e30f;
                float s1 = sacc[mi][ni][1] * 0.125f; if (!((w0 >> (sh + 1)) & 1)) s1 = -1.0e30f;
                float s2 = sacc[mi][ni][2] * 0.125f; if (!((w1 >> sh) & 1)) s2 = -1.0e30f;
                float s3 = sacc[mi][ni][3] * 0.125f; if (!((w1 >> (sh + 1)) & 1)) s3 = -1.0e30f;
                float p0 = __expf(s0), p1 = __expf(s1);
                float p2 = __expf(s2), p3 = __expf(s3);
                *(uint32_t*)(pptr[mi][0] + c * 128 + cb) = h2(p0, p1);
                *(uint32_t*)(pptr[mi][1] + c * 128 + cb) = h2(p2, p3);
                lacc[mi][0] += p0 + p1;
                lacc[mi][1] += p2 + p3;
                sacc[mi][ni][0] = p0; sacc[mi][ni][1] = p1;
                sacc[mi][ni][2] = p2; sacc[mi][ni][3] = p3;
            }
        }

#pragma unroll
        for (int j = 0; j < 4; j++) {
            uint32_t a0[2], a1[2], a2[2], a3[2];
#pragma unroll
            for (int mi = 0; mi < 2; mi++) {
                a0[mi] = h2(sacc[mi][2 * j][0], sacc[mi][2 * j][1]);
                a1[mi] = h2(sacc[mi][2 * j][2], sacc[mi][2 * j][3]);
                a2[mi] = h2(sacc[mi][2 * j + 1][0], sacc[mi][2 * j + 1][1]);
                a3[mi] = h2(sacc[mi][2 * j + 1][2], sacc[mi][2 * j + 1][3]);
            }
#pragma unroll
            for (int nii = 0; nii < 4; nii++) {
                uint32_t b0, b1, b2, b3;
                uint32_t a = vs_b[buf] + ((wk * 64 + j * 16 + bit3 + l7) * QP + nii * 16 + bit4) * 2;
                LDM4T(b0, b1, b2, b3, a);
                mma16(oacc[0][2 * nii],     a0[0], a1[0], a2[0], a3[0], b0, b1);
                mma16(oacc[1][2 * nii],     a0[1], a1[1], a2[1], a3[1], b0, b1);
                mma16(oacc[0][2 * nii + 1], a0[0], a1[0], a2[0], a3[0], b2, b3);
                mma16(oacc[1][2 * nii + 1], a0[1], a1[1], a2[1], a3[1], b2, b3);
            }
        }
    }

#pragma unroll
    for (int mi = 0; mi < 2; mi++)
#pragma unroll
        for (int hi = 0; hi < 2; hi++) {
            float v = lacc[mi][hi];
            v += __shfl_xor_sync(0xFFFFFFFF, v, 1);
            v += __shfl_xor_sync(0xFFFFFFFF, v, 2);
            if ((lane & 3) == 0)
                lred[wk * 128 + qb + mi * 16 + hi * 8 + qr] = v;
        }
    __syncthreads();

    if (wk == 1) {
#pragma unroll
        for (int mi = 0; mi < 2; mi++) {
            int row = qb + mi * 16 + qr;
#pragma unroll
            for (int ni = 0; ni < 8; ni++) {
                *(float2*)&Osm[row * 68 + ni * 8 + qc] =
                    make_float2(oacc[mi][ni][0], oacc[mi][ni][1]);
                *(float2*)&Osm[(row + 8) * 68 + ni * 8 + qc] =
                    make_float2(oacc[mi][ni][2], oacc[mi][ni][3]);
            }
        }
    }
    __syncthreads();

    if (wk == 0) {
#pragma unroll
        for (int mi = 0; mi < 2; mi++) {
#pragma unroll
            for (int hi = 0; hi < 2; hi++) {
                int rrow = qb + mi * 16 + hi * 8 + qr;
                float l = lred[rrow] + lred[128 + rrow];
                float inv = 1.0f / l;
                __half* og = g_ctx + (size_t)(b * LQn + q0 + rrow) * EE + h * DD;
#pragma unroll
                for (int ni = 0; ni < 8; ni++) {
                    float2 part = *(const float2*)&Osm[rrow * 68 + ni * 8 + qc];
                    *(uint32_t*)&og[ni * 8 + qc] = h2(
                        (oacc[mi][ni][hi * 2 + 0] + part.x) * inv,
                        (oacc[mi][ni][hi * 2 + 1] + part.y) * inv);
                }
                if ((lane & 3) == 0)
                    g_stats[(size_t)(b * HH + h) * LQn + q0 + rrow] = l;
            }
        }
    }
}

// ---------------- normalize ----------------
__global__ __launch_bounds__(256) void attn_norm(float* __restrict__ attn)
{
    size_t i8 = (size_t)blockIdx.x * blockDim.x + threadIdx.x;
    size_t row = (i8 * 8) >> 11;
    float invl = 1.0f / g_stats[row];
    uint4 pv = *(const uint4*)(g_P + i8 * 8);
    float2 f0 = __half22float2(*(__half2*)&pv.x);
    float2 f1 = __half22float2(*(__half2*)&pv.y);
    float2 f2 = __half22float2(*(__half2*)&pv.z);
    float2 f3 = __half22float2(*(__half2*)&pv.w);
    float4* op = (float4*)(attn + i8 * 8);
    op[0] = make_float4(f0.x * invl, f0.y * invl, f1.x * invl, f1.y * invl);
    op[1] = make_float4(f2.x * invl, f2.y * invl, f3.x * invl, f3.y * invl);
}

// ---------------- launch ----------------
extern "C" void kernel_launch(void* const* d_in, const int* in_sizes, int n_in,
                              void* d_out, int out_size)
{
    const float* q_in = (const float*)d_in[0];
    const float* k_in = (const float*)d_in[1];
    const float* v_in = (const float*)d_in[2];
    const int*   mask = (const int*)d_in[3];
    const float* Wq = (const float*)d_in[4];
    const float* bq = (const float*)d_in[5];
    const float* Wk = (const float*)d_in[6];
    const float* bk = (const float*)d_in[7];
    const float* Wv = (const float*)d_in[8];
    const float* bv = (const float*)d_in[9];
    const float* Wo = (const float*)d_in[10];
    const float* bo = (const float*)d_in[11];

    float* out = (float*)d_out;

    float* gSraw;
    cudaGetSymbolAddress((void**)&gSraw, g_Sraw);

    const size_t OUT_ELEMS = (size_t)BB * LQn * EE;
    const size_t ATT_ELEMS = (size_t)BB * HH * LQn * LKn;
    bool attn_is_output = ((size_t)out_size >= OUT_ELEMS + ATT_ELEMS);
    float* attnp = attn_is_output ? (out + OUT_ELEMS) : gSraw;

    cudaFuncSetAttribute(attn_tc, cudaFuncAttributeMaxDynamicSharedMemorySize, ATT_DYN);
    cudaFuncSetAttribute(gemm_qkv, cudaFuncAttributeMaxDynamicSharedMemorySize, GEMM_DYN);
    cudaFuncSetAttribute(gemm_out, cudaFuncAttributeMaxDynamicSharedMemorySize, GEMM_DYN);

    static cudaStream_t s2 = nullptr;
    static cudaEvent_t evFork = nullptr, evJoin = nullptr;
    if (!s2) {
        cudaStreamCreateWithFlags(&s2, cudaStreamNonBlocking);
        cudaEventCreateWithFlags(&evFork, cudaEventDisableTiming);
        cudaEventCreateWithFlags(&evJoin, cudaEventDisableTiming);
    }

    conv_w<<<dim3(EE * EE / 1024, 4), 256>>>(Wq, Wk, Wv, Wo);
    conv_x<<<dim3(BB * LQn * EE / 1024, 3), 256>>>(q_in, k_in, v_in);
    conv_mask<<<(int)((size_t)BB * LQn * LKn / 256), 256>>>(mask);

    dim3 qkvGrid(8, 32, 3);
    gemm_qkv<<<qkvGrid, 128, GEMM_DYN>>>(bq, bk, bv);

    dim3 attnGrid(LQn / 128, HH, BB);
    attn_tc<<<attnGrid, 256, ATT_DYN>>>();

    cudaEventRecord(evFork, 0);
    cudaStreamWaitEvent(s2, evFork, 0);

    size_t total8 = ATT_ELEMS / 8;
    attn_norm<<<(int)((total8 + 255) / 256), 256, 0, s2>>>(attnp);

    gemm_out<<<dim3(8, 32), 128, GEMM_DYN>>>(bo, out);

    cudaEventRecord(evJoin, s2);
    cudaStreamWaitEvent(0, evJoin, 0);
}